// round 11
// baseline (speedup 1.0000x reference)
#include <cuda_runtime.h>

// Problem constants
#define BQ    8192
#define NSUB  16
#define KC    1024
#define EDIM  16
#define DEPTHQ 3
#define DIMQ  256

// Output layout: [loss(1), z_q_out(B*256), onehot(B*16*1024), idx(B*16)]
#define OFF_LOSS   ((size_t)0)
#define OFF_ZQ     ((size_t)1)
#define OFF_ONEHOT ((size_t)(1 + BQ * DIMQ))
#define OFF_IDX    ((size_t)(OFF_ONEHOT + (size_t)BQ * NSUB * KC))

__device__ float g_P[(size_t)NSUB * KC * DIMQ];
__device__ int   g_idx[(size_t)BQ * NSUB * DEPTHQ];

// ---------------- packed f32x2 helpers ----------------
__device__ __forceinline__ unsigned long long pack2(float a, float b) {
    unsigned long long r;
    asm("mov.b64 %0, {%1,%2};" : "=l"(r) : "f"(a), "f"(b));
    return r;
}
__device__ __forceinline__ void fma2(unsigned long long& d, unsigned long long a, unsigned long long b) {
    asm("fma.rn.f32x2 %0, %1, %2, %0;" : "+l"(d) : "l"(a), "l"(b));
}
__device__ __forceinline__ unsigned long long fma2v(unsigned long long a, unsigned long long b, unsigned long long c) {
    unsigned long long r;
    asm("fma.rn.f32x2 %0, %1, %2, %3;" : "=l"(r) : "l"(a), "l"(b), "l"(c));
    return r;
}
__device__ __forceinline__ unsigned long long add2(unsigned long long a, unsigned long long b) {
    unsigned long long r;
    asm("add.rn.f32x2 %0, %1, %2;" : "=l"(r) : "l"(a), "l"(b));
    return r;
}
__device__ __forceinline__ void unpack2(unsigned long long v, float& lo, float& hi) {
    asm("mov.b64 {%0,%1}, %2;" : "=f"(lo), "=f"(hi) : "l"(v));
}

// ---------------- kernel 1: P precompute (+ zero loss slot) ----------------
__global__ void compute_P_kernel(const float* __restrict__ emb,
                                 const float* __restrict__ W,
                                 float* __restrict__ out) {
    if (blockIdx.x == 0 && threadIdx.x == 0) out[OFF_LOSS] = 0.0f;

    const int n  = blockIdx.x >> 6;
    const int k0 = (blockIdx.x & 63) * 16;
    const int j  = threadIdx.x;

    __shared__ float se[16 * EDIM];
    se[j] = emb[((size_t)n * KC + k0) * EDIM + j];

    float w[16];
#pragma unroll
    for (int i = 0; i < 16; i++) w[i] = W[(size_t)(n * 16 + i) * DIMQ + j];
    __syncthreads();

#pragma unroll
    for (int kk = 0; kk < 16; kk++) {
        float acc = 0.0f;
#pragma unroll
        for (int i = 0; i < 16; i++) acc = fmaf(se[kk * EDIM + i], w[i], acc);
        g_P[((size_t)n * KC + (k0 + kk)) * DIMQ + j] = acc;
    }
}

// ---------------- kernel 2: VQ search — deferred-epilogue pipelined scan ----------------
// grid (16 row-tiles of 512 rows, 16 n), 256 threads, 2 rows/thread, 2 blocks/SM.
#define NKP (KC / 2)
#define VQ_SMEM ((size_t)(NKP * EDIM * 8 + NKP * 8))

// Compute packed scores for code group KP2 (codes 4*KP2 .. 4*KP2+3) into
// SA0 (row A, codes +0/+1), SB0, SA1 (row A, codes +2/+3), SB1.
// Per lane: sequential fmaf chain i=0..15, then s = fmaf(-2,c,zsq)+es —
// bit-matches the reference contraction ordering.
#define SCORE_GROUP(KP2, SA0, SB0, SA1, SB1) do {                              \
    const ulonglong2* mv0 = (const ulonglong2*)(pc + (size_t)(2 * (KP2)) * EDIM); \
    const ulonglong2* mv1 = mv0 + 8;                                           \
    const ulonglong2 es2 = *((const ulonglong2*)(s_esq + 2 * (KP2)));          \
    unsigned long long aA0 = 0ull, aB0 = 0ull, aA1 = 0ull, aB1 = 0ull;         \
    _Pragma("unroll")                                                          \
    for (int c = 0; c < 4; c++) {                                              \
        ulonglong2 p0 = mv0[2 * c], q0 = mv0[2 * c + 1];                       \
        ulonglong2 p1 = mv1[2 * c], q1 = mv1[2 * c + 1];                       \
        const int i = 4 * c;                                                   \
        fma2(aA0, zdA[i + 0], p0.x); fma2(aB0, zdB[i + 0], p0.x);              \
        fma2(aA1, zdA[i + 0], p1.x); fma2(aB1, zdB[i + 0], p1.x);              \
        fma2(aA0, zdA[i + 1], p0.y); fma2(aB0, zdB[i + 1], p0.y);              \
        fma2(aA1, zdA[i + 1], p1.y); fma2(aB1, zdB[i + 1], p1.y);              \
        fma2(aA0, zdA[i + 2], q0.x); fma2(aB0, zdB[i + 2], q0.x);              \
        fma2(aA1, zdA[i + 2], q1.x); fma2(aB1, zdB[i + 2], q1.x);              \
        fma2(aA0, zdA[i + 3], q0.y); fma2(aB0, zdB[i + 3], q0.y);              \
        fma2(aA1, zdA[i + 3], q1.y); fma2(aB1, zdB[i + 3], q1.y);              \
    }                                                                          \
    SA0 = add2(fma2v(aA0, NEG2, zsqA2), es2.x);                                \
    SB0 = add2(fma2v(aB0, NEG2, zsqB2), es2.x);                                \
    SA1 = add2(fma2v(aA1, NEG2, zsqA2), es2.y);                                \
    SB1 = add2(fma2v(aB1, NEG2, zsqB2), es2.y);                                \
} while (0)

// Epilogue for a (deferred) score group at base code KB.
// Common path: 2-deep fminf tree + one FSETP per row. Rare branch replays the
// exact sequential update. bd is NOT stored across groups: by monotonicity of
// sqrt(max(.,0)), running bd == sqrt(max(running bs,0)) at every group entry,
// so it is recomputed there. Tie (dv == bd) keeps the earlier index — exactly
// jnp.argmin over d = sqrt(max(s,0)) with first-index ties.
#define EPILOGUE(PA0, PB0, PA1, PB1, KB) do {                                  \
    float sA0l, sA0h, sA1l, sA1h, sB0l, sB0h, sB1l, sB1h;                      \
    unpack2(PA0, sA0l, sA0h); unpack2(PB0, sB0l, sB0h);                        \
    unpack2(PA1, sA1l, sA1h); unpack2(PB1, sB1l, sB1h);                        \
    const float tA = fminf(fminf(sA0l, sA0h), fminf(sA1l, sA1h));              \
    const float tB = fminf(fminf(sB0l, sB0h), fminf(sB1l, sB1h));              \
    const bool cA = tA < bsA;                                                  \
    const bool cB = tB < bsB;                                                  \
    if (cA | cB) {                                                             \
        if (cA) {                                                              \
            float bsRun = bsA, bdRun = sqrtf(fmaxf(bsA, 0.0f));                \
            if (sA0l < bsRun) { float dv = sqrtf(fmaxf(sA0l, 0.0f)); if (dv < bdRun) { bdRun = dv; bkA = (KB); }     bsRun = sA0l; } \
            if (sA0h < bsRun) { float dv = sqrtf(fmaxf(sA0h, 0.0f)); if (dv < bdRun) { bdRun = dv; bkA = (KB) + 1; } bsRun = sA0h; } \
            if (sA1l < bsRun) { float dv = sqrtf(fmaxf(sA1l, 0.0f)); if (dv < bdRun) { bdRun = dv; bkA = (KB) + 2; } bsRun = sA1l; } \
            if (sA1h < bsRun) { float dv = sqrtf(fmaxf(sA1h, 0.0f)); if (dv < bdRun) { bdRun = dv; bkA = (KB) + 3; } bsRun = sA1h; } \
        }                                                                      \
        if (cB) {                                                              \
            float bsRun = bsB, bdRun = sqrtf(fmaxf(bsB, 0.0f));                \
            if (sB0l < bsRun) { float dv = sqrtf(fmaxf(sB0l, 0.0f)); if (dv < bdRun) { bdRun = dv; bkB = (KB); }     bsRun = sB0l; } \
            if (sB0h < bsRun) { float dv = sqrtf(fmaxf(sB0h, 0.0f)); if (dv < bdRun) { bdRun = dv; bkB = (KB) + 1; } bsRun = sB0h; } \
            if (sB1l < bsRun) { float dv = sqrtf(fmaxf(sB1l, 0.0f)); if (dv < bdRun) { bdRun = dv; bkB = (KB) + 2; } bsRun = sB1l; } \
            if (sB1h < bsRun) { float dv = sqrtf(fmaxf(sB1h, 0.0f)); if (dv < bdRun) { bdRun = dv; bkB = (KB) + 3; } bsRun = sB1h; } \
        }                                                                      \
    }                                                                          \
    bsA = fminf(bsA, tA);                                                      \
    bsB = fminf(bsB, tB);                                                      \
} while (0)

__global__ void __launch_bounds__(256, 2)
vq_kernel(const float* __restrict__ z,
          const float* __restrict__ emb,
          float* __restrict__ out) {
    extern __shared__ unsigned long long sm[];
    unsigned long long* pc = sm;                                 // pc[kp*16 + i] = (e[2kp][i], e[2kp+1][i])
    unsigned long long* s_esq = sm + (size_t)NKP * EDIM;         // (esq[2kp], esq[2kp+1])

    const float* pcf = (const float*)pc;  // e[k][i] at pcf[((k>>1)*16 + i)*2 + (k&1)]

    const int n = blockIdx.y;
    const int rowbase = blockIdx.x * 512;
    const int tid = threadIdx.x;

    // Build paired codebook + esq (sequential fmaf chain per code — matches ref)
    for (int kp = tid; kp < NKP; kp += 256) {
        const float* e0 = emb + ((size_t)n * KC + 2 * kp) * EDIM;
        const float* e1 = e0 + EDIM;
        float esq0 = 0.0f, esq1 = 0.0f;
        unsigned long long* m = pc + (size_t)kp * EDIM;
#pragma unroll
        for (int i = 0; i < 16; i++) {
            float v0 = __ldg(e0 + i);
            float v1 = __ldg(e1 + i);
            esq0 = fmaf(v0, v0, esq0);
            esq1 = fmaf(v1, v1, esq1);
            m[i] = pack2(v0, v1);
        }
        s_esq[kp] = pack2(esq0, esq1);
    }
    __syncthreads();

    // Two rows per thread: A = rowbase+tid, B = rowbase+256+tid.
    const int bA = rowbase + tid;
    const int bB = rowbase + 256 + tid;
    unsigned long long zdA[16], zdB[16];
    unsigned long long zsqA2, zsqB2;
    {
        const float* zA = z + (size_t)bA * DIMQ + n * EDIM;
        const float* zB = z + (size_t)bB * DIMQ + n * EDIM;
        float sA = 0.0f, sB = 0.0f;
#pragma unroll
        for (int i = 0; i < 16; i++) {
            float a = zA[i], b = zB[i];
            zdA[i] = pack2(a, a);
            zdB[i] = pack2(b, b);
            sA = fmaf(a, a, sA);
            sB = fmaf(b, b, sB);
        }
        zsqA2 = pack2(sA, sA);
        zsqB2 = pack2(sB, sB);
    }

    const unsigned long long NEG2 = 0xC0000000C0000000ull;  // (-2.f, -2.f)

    int bkA_last = 0, bkB_last = 0;

    for (int d = 0; d < DEPTHQ; d++) {
        // Onehot zero-fill, chunk d (indices-independent; overlaps DRAM with scan)
        {
            const int r0 = d * 171;
            const int r1 = (d == 2) ? 512 : (r0 + 171);
            for (int rl = r0; rl < r1; rl++) {
                float* dst = out + OFF_ONEHOT + ((size_t)(rowbase + rl) * NSUB + n) * KC;
                dst[tid]       = 0.0f;
                dst[tid + 256] = 0.0f;
                dst[tid + 512] = 0.0f;
                dst[tid + 768] = 0.0f;
            }
        }

        float bsA = 3.4e38f, bsB = 3.4e38f;
        int bkA = 0, bkB = 0;

        // Deferred-epilogue pipeline: iteration kp2 issues its FMA chains,
        // then retires the epilogue of kp2-1 (whose scores are long ready),
        // so the branch never waits on an in-flight FMA chain.
        unsigned long long pA0, pB0, pA1, pB1;   // deferred scores
        SCORE_GROUP(0, pA0, pB0, pA1, pB1);

#pragma unroll 1
        for (int kp2 = 1; kp2 < NKP / 2; ++kp2) {
            unsigned long long qA0, qB0, qA1, qB1;
            SCORE_GROUP(kp2, qA0, qB0, qA1, qB1);
            EPILOGUE(pA0, pB0, pA1, pB1, 4 * kp2 - 4);
            pA0 = qA0; pB0 = qB0; pA1 = qA1; pB1 = qB1;
        }
        EPILOGUE(pA0, pB0, pA1, pB1, 4 * (NKP / 2) - 4);

        // Residual update (one fp32 sub per component, matching ref), zsq refresh
        {
            const size_t baseA = ((size_t)(bkA >> 1) * EDIM) * 2 + (bkA & 1);
            const size_t baseB = ((size_t)(bkB >> 1) * EDIM) * 2 + (bkB & 1);
            float sA = 0.0f, sB = 0.0f;
#pragma unroll
            for (int i = 0; i < 16; i++) {
                float a, dummy, b;
                unpack2(zdA[i], a, dummy);
                unpack2(zdB[i], b, dummy);
                a = a - pcf[baseA + 2 * i];
                b = b - pcf[baseB + 2 * i];
                sA = fmaf(a, a, sA);
                sB = fmaf(b, b, sB);
                zdA[i] = pack2(a, a);
                zdB[i] = pack2(b, b);
            }
            zsqA2 = pack2(sA, sA);
            zsqB2 = pack2(sB, sB);
        }

        g_idx[((size_t)bA * NSUB + n) * DEPTHQ + d] = bkA;
        g_idx[((size_t)bB * NSUB + n) * DEPTHQ + d] = bkB;
        if (d == DEPTHQ - 1) {
            bkA_last = bkA;
            bkB_last = bkB;
            out[OFF_IDX + (size_t)bA * NSUB + n] = (float)bkA;
            out[OFF_IDX + (size_t)bB * NSUB + n] = (float)bkB;
        }
    }

    // All zero-fills in this block precede the last scan; sync orders them
    // against the single-one writes to the same rows.
    __syncthreads();
    out[OFF_ONEHOT + ((size_t)bA * NSUB + n) * KC + bkA_last] = 1.0f;
    out[OFF_ONEHOT + ((size_t)bB * NSUB + n) * KC + bkB_last] = 1.0f;
}

// ---------------- kernel 3: z_q gather + z_q_out + loss ----------------
__global__ void gather_out_kernel(const float* __restrict__ z,
                                  const float* __restrict__ bias,
                                  float* __restrict__ out) {
    const int b = blockIdx.x;
    const int j = threadIdx.x;
    __shared__ int sidx[48];
    __shared__ float sred[8];

    if (j < 48) sidx[j] = g_idx[(size_t)b * 48 + j];
    __syncthreads();

    float acc = 0.0f;
#pragma unroll
    for (int n = 0; n < NSUB; n++) {
#pragma unroll
        for (int d = 0; d < DEPTHQ; d++) {
            const int k = sidx[n * 3 + d];
            acc += g_P[(((size_t)n << 10) + k) * DIMQ + j];
        }
    }
    const float zq = acc * (1.0f / 3.0f) + bias[j];
    const float zv = z[(size_t)b * DIMQ + j];
    const float diff = zq - zv;
    out[OFF_ZQ + (size_t)b * DIMQ + j] = zv + diff;

    float p = diff * diff;
#pragma unroll
    for (int off = 16; off > 0; off >>= 1) p += __shfl_down_sync(0xffffffffu, p, off);
    if ((j & 31) == 0) sred[j >> 5] = p;
    __syncthreads();
    if (j == 0) {
        float s = 0.0f;
#pragma unroll
        for (int i = 0; i < 8; i++) s += sred[i];
        atomicAdd(out + OFF_LOSS, s * (1.25f / (float)(BQ * DIMQ)));
    }
}

// ---------------- launcher ----------------
extern "C" void kernel_launch(void* const* d_in, const int* in_sizes, int n_in,
                              void* d_out, int out_size) {
    const float* z    = (const float*)d_in[0];
    const float* emb  = (const float*)d_in[1];
    const float* W    = (const float*)d_in[2];
    const float* bias = (const float*)d_in[3];
    float* out = (float*)d_out;

    (void)in_sizes; (void)n_in; (void)out_size;

    // vq first (independent of P) so ncu's sampled launch lands on vq.
    cudaFuncSetAttribute(vq_kernel, cudaFuncAttributeMaxDynamicSharedMemorySize, (int)VQ_SMEM);
    vq_kernel<<<dim3(16, 16), 256, VQ_SMEM>>>(z, emb, out);

    compute_P_kernel<<<1024, 256>>>(emb, W, out);

    gather_out_kernel<<<BQ, 256>>>(z, bias, out);
}